// round 11
// baseline (speedup 1.0000x reference)
#include <cuda_runtime.h>
#include <math.h>
#include <stdint.h>

#define N_TOK   8192
#define D_MODEL 1024
#define H_DIM   512
#define N_EXP   8
#define TOPK    2
#define N_ASSIGN (N_TOK * TOPK)
#define TILE_M  128
#define MAX_TILES (N_ASSIGN / TILE_M + N_EXP)   // 136

// ------------------- device scratch -------------------
__device__ float g_h[(size_t)N_ASSIGN * H_DIM];
__device__ float g_y[(size_t)N_ASSIGN * D_MODEL];
__device__ int   g_counts[N_EXP];
__device__ int   g_offsets[N_EXP + 1];
__device__ int   g_cursors[N_EXP];
__device__ int   g_rowToken[N_ASSIGN];
__device__ int   g_tokRow[N_TOK * TOPK];
__device__ float g_tokw[N_TOK];
__device__ int   g_tokExperts[N_TOK * TOPK];
__device__ int   g_tileExpert[MAX_TILES];
__device__ int   g_tileRowStart[MAX_TILES];
__device__ int   g_tileRows[MAX_TILES];
__device__ int   g_numTiles;

// ------------------- helpers -------------------
__device__ __forceinline__ uint32_t f2tf(float f) {
    uint32_t u;
    asm("cvt.rna.tf32.f32 %0, %1;" : "=r"(u) : "f"(f));
    return u;
}
__device__ __forceinline__ void mma_tf32(float& c0, float& c1, float& c2, float& c3,
                                         uint32_t a0, uint32_t a1, uint32_t a2, uint32_t a3,
                                         uint32_t b0, uint32_t b1) {
    asm volatile("mma.sync.aligned.m16n8k8.row.col.f32.tf32.tf32.f32 "
                 "{%0,%1,%2,%3}, {%4,%5,%6,%7}, {%8,%9}, {%0,%1,%2,%3};"
                 : "+f"(c0), "+f"(c1), "+f"(c2), "+f"(c3)
                 : "r"(a0), "r"(a1), "r"(a2), "r"(a3), "r"(b0), "r"(b1));
}
__device__ __forceinline__ float gelu_exact(float v) {
    return 0.5f * v * (1.0f + erff(v * 0.70710678118654752f));
}

// ------------------- init (counters only; out fully overwritten by combine) -------------------
__global__ void init_kernel() {
    if (threadIdx.x < N_EXP) g_counts[threadIdx.x] = 0;
}

// ------------------- gating -------------------
__global__ void gate_kernel(const float* __restrict__ x, const float* __restrict__ gw) {
    int n = blockIdx.x;
    int tid = threadIdx.x;
    const float* xr = x + (size_t)n * D_MODEL;
    float acc[N_EXP];
#pragma unroll
    for (int e = 0; e < N_EXP; e++) acc[e] = 0.f;
    for (int d = tid; d < D_MODEL; d += 256) {
        float xv = xr[d];
        const float* g = gw + d * N_EXP;
#pragma unroll
        for (int e = 0; e < N_EXP; e++) acc[e] += xv * g[e];
    }
#pragma unroll
    for (int off = 16; off > 0; off >>= 1)
#pragma unroll
        for (int e = 0; e < N_EXP; e++)
            acc[e] += __shfl_down_sync(0xffffffffu, acc[e], off);
    __shared__ float s[8][N_EXP];
    int w = tid >> 5, l = tid & 31;
    if (l == 0)
#pragma unroll
        for (int e = 0; e < N_EXP; e++) s[w][e] = acc[e];
    __syncthreads();
    if (tid == 0) {
        float p[N_EXP];
#pragma unroll
        for (int e = 0; e < N_EXP; e++) {
            float v = 0.f;
#pragma unroll
            for (int ww = 0; ww < 8; ww++) v += s[ww][e];
            p[e] = v;
        }
        float mx = p[0];
#pragma unroll
        for (int e = 1; e < N_EXP; e++) mx = fmaxf(mx, p[e]);
        float sum = 0.f;
#pragma unroll
        for (int e = 0; e < N_EXP; e++) { p[e] = expf(p[e] - mx); sum += p[e]; }
        float inv = 1.f / sum;
#pragma unroll
        for (int e = 0; e < N_EXP; e++) p[e] *= inv;
        int i1 = 0;
#pragma unroll
        for (int e = 1; e < N_EXP; e++) if (p[e] > p[i1]) i1 = e;
        int i2 = (i1 == 0) ? 1 : 0;
#pragma unroll
        for (int e = 0; e < N_EXP; e++) if (e != i1 && p[e] > p[i2]) i2 = e;
        g_tokw[n] = p[i1] + p[i2];
        g_tokExperts[2 * n + 0] = i1;
        g_tokExperts[2 * n + 1] = i2;
        atomicAdd(&g_counts[i1], 1);
        atomicAdd(&g_counts[i2], 1);
    }
}

// ------------------- setup + scatter -------------------
__global__ void setup_kernel() {
    int off = 0;
    for (int e = 0; e < N_EXP; e++) { g_offsets[e] = off; g_cursors[e] = off; off += g_counts[e]; }
    g_offsets[N_EXP] = off;
    int t = 0;
    for (int e = 0; e < N_EXP; e++) {
        int c = g_counts[e];
        for (int r = 0; r < c; r += TILE_M) {
            g_tileExpert[t] = e; g_tileRowStart[t] = g_offsets[e] + r;
            g_tileRows[t] = min(TILE_M, c - r); t++;
        }
    }
    g_numTiles = t;
}
__global__ void scatter_kernel() {
    int n = blockIdx.x * blockDim.x + threadIdx.x;
    if (n >= N_TOK) return;
#pragma unroll
    for (int k = 0; k < TOPK; k++) {
        int e = g_tokExperts[2 * n + k];
        int pos = atomicAdd(&g_cursors[e], 1);
        g_rowToken[pos] = n;
        g_tokRow[2 * n + k] = pos;
    }
}

// ------------------- tf32 mma.sync grouped GEMM (R4-proven core) -------------------
// Tile 128(M) x 128(N), BK=16. 8 warps: warp_m = wid&1 (x64), warp_n = wid>>1 (x32).
// Warp tile 64x32 -> 4x4 grid of m16n8k8.
// SMEM: As[2][128][20] (bank=4m+k, conflict-free), Bs[2][16][136] (bank=8k+n, conflict-free).
#define BK 16
#define ASTR 20
#define BSTR 136

struct Frag { float c[4][4][4]; };  // [mi][ni][reg]

template <int KDIM, bool FC1>
__device__ __forceinline__ void gemm_core(
    const float* __restrict__ aBase,   // FC1: x (gathered); FC2: g_h
    const float* __restrict__ bBase,   // weight [KDIM][N_total] row-major for this expert
    int nTotal, int n0, int rs, int nr, Frag& F)
{
    __shared__ uint32_t As[2][128][ASTR];
    __shared__ uint32_t Bs[2][BK][BSTR];

    int tid = threadIdx.x;
    int lane = tid & 31, wid = tid >> 5;
    int quad = lane >> 2, t4 = lane & 3;
    int wm = (wid & 1) * 64, wn = (wid >> 1) * 32;

    // A gather setup: 2 threads per row, 8 floats (2 float4) each
    int arow = tid >> 1;
    int acol0 = (tid & 1) * 8;
    const float* aptr;
    bool avalid;
    if (FC1) {
        avalid = arow < nr;
        aptr = avalid ? (aBase + (size_t)g_rowToken[rs + arow] * KDIM) : aBase;
    } else {
        avalid = true;
        int ar = rs + arow; if (ar >= N_ASSIGN) ar = N_ASSIGN - 1;
        aptr = aBase + (size_t)ar * KDIM;
    }
    // B: 16 threads/row group: row = tid>>4 (0..15), 2 float4 at cols (tid&15)*8
    int brow = tid >> 4;
    int bcol0 = (tid & 15) * 8;
    const float* bptr = bBase + (size_t)brow * nTotal + n0 + bcol0;

#pragma unroll
    for (int mi = 0; mi < 4; mi++)
#pragma unroll
        for (int ni = 0; ni < 4; ni++)
#pragma unroll
            for (int rr = 0; rr < 4; rr++) F.c[mi][ni][rr] = 0.f;

    // ---- prologue: load tile 0 ----
    {
#pragma unroll
        for (int j = 0; j < 2; j++) {
            float4 v = avalid ? *(const float4*)(aptr + acol0 + j * 4)
                              : make_float4(0.f, 0.f, 0.f, 0.f);
            uint32_t* d = &As[0][arow][acol0 + j * 4];
            d[0] = f2tf(v.x); d[1] = f2tf(v.y); d[2] = f2tf(v.z); d[3] = f2tf(v.w);
        }
#pragma unroll
        for (int j = 0; j < 2; j++) {
            float4 v = *(const float4*)(bptr + j * 4);
            uint32_t* d = &Bs[0][brow][bcol0 + j * 4];
            d[0] = f2tf(v.x); d[1] = f2tf(v.y); d[2] = f2tf(v.z); d[3] = f2tf(v.w);
        }
    }
    __syncthreads();

    const int NT = KDIM / BK;
    for (int t = 0; t < NT; t++) {
        int s = t & 1;
        float4 na[2], nb[2];
        bool more = (t + 1) < NT;
        if (more) {
            int k0 = (t + 1) * BK;
#pragma unroll
            for (int j = 0; j < 2; j++)
                na[j] = avalid ? *(const float4*)(aptr + k0 + acol0 + j * 4)
                               : make_float4(0.f, 0.f, 0.f, 0.f);
#pragma unroll
            for (int j = 0; j < 2; j++)
                nb[j] = *(const float4*)(bptr + (size_t)k0 * nTotal + j * 4);
        }
        // ---- compute on stage s ----
#pragma unroll
        for (int kk = 0; kk < BK / 8; kk++) {
            uint32_t a[4][4], b[4][2];
#pragma unroll
            for (int mi = 0; mi < 4; mi++) {
                int r0 = wm + mi * 16 + quad;
                a[mi][0] = As[s][r0][kk * 8 + t4];
                a[mi][1] = As[s][r0 + 8][kk * 8 + t4];
                a[mi][2] = As[s][r0][kk * 8 + t4 + 4];
                a[mi][3] = As[s][r0 + 8][kk * 8 + t4 + 4];
            }
#pragma unroll
            for (int ni = 0; ni < 4; ni++) {
                int cc = wn + ni * 8 + quad;
                b[ni][0] = Bs[s][kk * 8 + t4][cc];
                b[ni][1] = Bs[s][kk * 8 + t4 + 4][cc];
            }
#pragma unroll
            for (int mi = 0; mi < 4; mi++)
#pragma unroll
                for (int ni = 0; ni < 4; ni++)
                    mma_tf32(F.c[mi][ni][0], F.c[mi][ni][1], F.c[mi][ni][2], F.c[mi][ni][3],
                             a[mi][0], a[mi][1], a[mi][2], a[mi][3],
                             b[ni][0], b[ni][1]);
        }
        // ---- store next stage ----
        if (more) {
            int s1 = s ^ 1;
#pragma unroll
            for (int j = 0; j < 2; j++) {
                uint32_t* d = &As[s1][arow][acol0 + j * 4];
                d[0] = f2tf(na[j].x); d[1] = f2tf(na[j].y); d[2] = f2tf(na[j].z); d[3] = f2tf(na[j].w);
            }
#pragma unroll
            for (int j = 0; j < 2; j++) {
                uint32_t* d = &Bs[s1][brow][bcol0 + j * 4];
                d[0] = f2tf(nb[j].x); d[1] = f2tf(nb[j].y); d[2] = f2tf(nb[j].z); d[3] = f2tf(nb[j].w);
            }
        }
        __syncthreads();
    }
}

// fc1: h = gelu(x_gathered @ w1[e] + b1[e]); grid (MAX_TILES, H_DIM/128)
__global__ void __launch_bounds__(256, 2)
fc1_mma(const float* __restrict__ x, const float* __restrict__ w1,
        const float* __restrict__ b1) {
    int tile = blockIdx.x;
    if (tile >= g_numTiles) return;
    int e = g_tileExpert[tile], rs = g_tileRowStart[tile], nr = g_tileRows[tile];
    int n0 = blockIdx.y * 128;

    Frag F;
    gemm_core<D_MODEL, true>(x, w1 + (size_t)e * D_MODEL * H_DIM, H_DIM, n0, rs, nr, F);

    int tid = threadIdx.x, lane = tid & 31, wid = tid >> 5;
    int quad = lane >> 2, t4 = lane & 3;
    int wm = (wid & 1) * 64, wn = (wid >> 1) * 32;
    const float* b1e = b1 + e * H_DIM + n0;
#pragma unroll
    for (int mi = 0; mi < 4; mi++) {
#pragma unroll
        for (int half = 0; half < 2; half++) {
            int m = wm + mi * 16 + quad + half * 8;
            if (m < nr) {
                float* hrow = g_h + (size_t)(rs + m) * H_DIM + n0;
#pragma unroll
                for (int ni = 0; ni < 4; ni++) {
                    int cc = wn + ni * 8 + 2 * t4;
                    float v0 = F.c[mi][ni][half * 2 + 0] + b1e[cc];
                    float v1 = F.c[mi][ni][half * 2 + 1] + b1e[cc + 1];
                    *(float2*)(hrow + cc) = make_float2(gelu_exact(v0), gelu_exact(v1));
                }
            }
        }
    }
}

// fc2: y_row = h @ w2[e] + b2[e]  (plain stores; combined later); grid (MAX_TILES, D_MODEL/128)
__global__ void __launch_bounds__(256, 2)
fc2_mma(const float* __restrict__ w2, const float* __restrict__ b2) {
    int tile = blockIdx.x;
    if (tile >= g_numTiles) return;
    int e = g_tileExpert[tile], rs = g_tileRowStart[tile], nr = g_tileRows[tile];
    int n0 = blockIdx.y * 128;

    Frag F;
    gemm_core<H_DIM, false>(g_h, w2 + (size_t)e * H_DIM * D_MODEL, D_MODEL, n0, rs, nr, F);

    int tid = threadIdx.x, lane = tid & 31, wid = tid >> 5;
    int quad = lane >> 2, t4 = lane & 3;
    int wm = (wid & 1) * 64, wn = (wid >> 1) * 32;
    const float* b2e = b2 + e * D_MODEL + n0;
#pragma unroll
    for (int mi = 0; mi < 4; mi++) {
#pragma unroll
        for (int half = 0; half < 2; half++) {
            int m = wm + mi * 16 + quad + half * 8;
            if (m < nr) {
                float* yrow = g_y + (size_t)(rs + m) * D_MODEL + n0;
#pragma unroll
                for (int ni = 0; ni < 4; ni++) {
                    int cc = wn + ni * 8 + 2 * t4;
                    float v0 = F.c[mi][ni][half * 2 + 0] + b2e[cc];
                    float v1 = F.c[mi][ni][half * 2 + 1] + b2e[cc + 1];
                    *(float2*)(yrow + cc) = make_float2(v0, v1);
                }
            }
        }
    }
}

// ------------------- combine: out[n] = tokw[n] * (y[r0] + y[r1]) -------------------
__global__ void combine_kernel(float* __restrict__ out) {
    int idx = blockIdx.x * blockDim.x + threadIdx.x;   // over N_TOK * D_MODEL / 4
    if (idx >= N_TOK * (D_MODEL / 4)) return;
    int n = idx >> 8;                 // D_MODEL/4 = 256
    int c4 = idx & 255;
    int r0 = g_tokRow[2 * n + 0];
    int r1 = g_tokRow[2 * n + 1];
    float w = g_tokw[n];
    float4 a = ((const float4*)(g_y + (size_t)r0 * D_MODEL))[c4];
    float4 b = ((const float4*)(g_y + (size_t)r1 * D_MODEL))[c4];
    float4 o;
    o.x = w * (a.x + b.x); o.y = w * (a.y + b.y);
    o.z = w * (a.z + b.z); o.w = w * (a.w + b.w);
    ((float4*)out)[idx] = o;
}

// ------------------- launch -------------------
extern "C" void kernel_launch(void* const* d_in, const int* in_sizes, int n_in,
                              void* d_out, int out_size) {
    const float* x      = (const float*)d_in[0];
    const float* gate_w = (const float*)d_in[1];
    const float* w1     = (const float*)d_in[2];
    const float* b1     = (const float*)d_in[3];
    const float* w2     = (const float*)d_in[4];
    const float* b2     = (const float*)d_in[5];
    float* out = (float*)d_out;

    init_kernel<<<1, 32>>>();
    gate_kernel<<<N_TOK, 256>>>(x, gate_w);
    setup_kernel<<<1, 1>>>();
    scatter_kernel<<<(N_TOK + 255) / 256, 256>>>();
    {
        dim3 g(MAX_TILES, H_DIM / 128);
        fc1_mma<<<g, 256>>>(x, w1, b1);
    }
    {
        dim3 g(MAX_TILES, D_MODEL / 128);
        fc2_mma<<<g, 256>>>(w2, b2);
    }
    combine_kernel<<<(N_TOK * (D_MODEL / 4) + 255) / 256, 256>>>(out);
}

// round 14
// speedup vs baseline: 1.4729x; 1.4729x over previous
#include <cuda_runtime.h>
#include <math.h>
#include <stdint.h>

#define N_TOK   8192
#define D_MODEL 1024
#define H_DIM   512
#define N_EXP   8
#define TOPK    2
#define N_ASSIGN (N_TOK * TOPK)
#define TILE_M  128
#define MAX_TILES (N_ASSIGN / TILE_M + N_EXP)   // 136

// ------------------- device scratch -------------------
__device__ float g_h[(size_t)N_ASSIGN * H_DIM];
__device__ int   g_counts[N_EXP];
__device__ int   g_offsets[N_EXP + 1];
__device__ int   g_cursors[N_EXP];
__device__ int   g_rowToken[N_ASSIGN];
__device__ float g_tokw[N_TOK];
__device__ int   g_tokExperts[N_TOK * TOPK];
__device__ int   g_tileExpert[MAX_TILES];
__device__ int   g_tileRowStart[MAX_TILES];
__device__ int   g_tileRows[MAX_TILES];
__device__ int   g_numTiles;

// ------------------- helpers -------------------
__device__ __forceinline__ uint32_t f2tf(float f) {
    uint32_t u;
    asm("cvt.rna.tf32.f32 %0, %1;" : "=r"(u) : "f"(f));
    return u;
}
__device__ __forceinline__ void mma_tf32(float& c0, float& c1, float& c2, float& c3,
                                         uint32_t a0, uint32_t a1, uint32_t a2, uint32_t a3,
                                         uint32_t b0, uint32_t b1) {
    asm volatile("mma.sync.aligned.m16n8k8.row.col.f32.tf32.tf32.f32 "
                 "{%0,%1,%2,%3}, {%4,%5,%6,%7}, {%8,%9}, {%0,%1,%2,%3};"
                 : "+f"(c0), "+f"(c1), "+f"(c2), "+f"(c3)
                 : "r"(a0), "r"(a1), "r"(a2), "r"(a3), "r"(b0), "r"(b1));
}
__device__ __forceinline__ void cp16(uint32_t dst, const void* src) {
    asm volatile("cp.async.cg.shared.global [%0], [%1], 16;" :: "r"(dst), "l"(src));
}
// src-size form: copies src_sz bytes (0 or 16), zero-fills the remainder of 16B
__device__ __forceinline__ void cp16z(uint32_t dst, const void* src, int src_sz) {
    asm volatile("cp.async.cg.shared.global [%0], [%1], 16, %2;"
                 :: "r"(dst), "l"(src), "r"(src_sz));
}
__device__ __forceinline__ void cp_commit() { asm volatile("cp.async.commit_group;" ::: "memory"); }
template <int N>
__device__ __forceinline__ void cp_wait() { asm volatile("cp.async.wait_group %0;" :: "n"(N) : "memory"); }
__device__ __forceinline__ float gelu_exact(float v) {
    return 0.5f * v * (1.0f + erff(v * 0.70710678118654752f));
}

// ------------------- init: zero output + counters (atomic epilogue needs zeros) ----
__global__ void init_kernel(float* __restrict__ out) {
    int idx = blockIdx.x * blockDim.x + threadIdx.x;
    if (idx < (N_TOK * D_MODEL) / 4)
        ((float4*)out)[idx] = make_float4(0.f, 0.f, 0.f, 0.f);
    if (idx < N_EXP) g_counts[idx] = 0;
}

// ------------------- gating -------------------
__global__ void gate_kernel(const float* __restrict__ x, const float* __restrict__ gw) {
    int n = blockIdx.x;
    int tid = threadIdx.x;
    const float* xr = x + (size_t)n * D_MODEL;
    float acc[N_EXP];
#pragma unroll
    for (int e = 0; e < N_EXP; e++) acc[e] = 0.f;
    for (int d = tid; d < D_MODEL; d += 256) {
        float xv = xr[d];
        const float* g = gw + d * N_EXP;
#pragma unroll
        for (int e = 0; e < N_EXP; e++) acc[e] += xv * g[e];
    }
#pragma unroll
    for (int off = 16; off > 0; off >>= 1)
#pragma unroll
        for (int e = 0; e < N_EXP; e++)
            acc[e] += __shfl_down_sync(0xffffffffu, acc[e], off);
    __shared__ float s[8][N_EXP];
    int w = tid >> 5, l = tid & 31;
    if (l == 0)
#pragma unroll
        for (int e = 0; e < N_EXP; e++) s[w][e] = acc[e];
    __syncthreads();
    if (tid == 0) {
        float p[N_EXP];
#pragma unroll
        for (int e = 0; e < N_EXP; e++) {
            float v = 0.f;
#pragma unroll
            for (int ww = 0; ww < 8; ww++) v += s[ww][e];
            p[e] = v;
        }
        float mx = p[0];
#pragma unroll
        for (int e = 1; e < N_EXP; e++) mx = fmaxf(mx, p[e]);
        float sum = 0.f;
#pragma unroll
        for (int e = 0; e < N_EXP; e++) { p[e] = expf(p[e] - mx); sum += p[e]; }
        float inv = 1.f / sum;
#pragma unroll
        for (int e = 0; e < N_EXP; e++) p[e] *= inv;
        int i1 = 0;
#pragma unroll
        for (int e = 1; e < N_EXP; e++) if (p[e] > p[i1]) i1 = e;
        int i2 = (i1 == 0) ? 1 : 0;
#pragma unroll
        for (int e = 0; e < N_EXP; e++) if (e != i1 && p[e] > p[i2]) i2 = e;
        g_tokw[n] = p[i1] + p[i2];
        g_tokExperts[2 * n + 0] = i1;
        g_tokExperts[2 * n + 1] = i2;
        atomicAdd(&g_counts[i1], 1);
        atomicAdd(&g_counts[i2], 1);
    }
}

// ------------------- setup + scatter -------------------
__global__ void setup_kernel() {
    int off = 0;
    for (int e = 0; e < N_EXP; e++) { g_offsets[e] = off; g_cursors[e] = off; off += g_counts[e]; }
    g_offsets[N_EXP] = off;
    int t = 0;
    for (int e = 0; e < N_EXP; e++) {
        int c = g_counts[e];
        for (int r = 0; r < c; r += TILE_M) {
            g_tileExpert[t] = e; g_tileRowStart[t] = g_offsets[e] + r;
            g_tileRows[t] = min(TILE_M, c - r); t++;
        }
    }
    g_numTiles = t;
}
__global__ void scatter_kernel() {
    int n = blockIdx.x * blockDim.x + threadIdx.x;
    if (n >= N_TOK) return;
#pragma unroll
    for (int k = 0; k < TOPK; k++) {
        int e = g_tokExperts[2 * n + k];
        int pos = atomicAdd(&g_cursors[e], 1);
        g_rowToken[pos] = n;
    }
}

// ------------------- tf32 mma.sync grouped GEMM, 3-stage cp.async, BK=32 -------------------
// Tile 128x128. 8 warps: warp_m = wid&1 (x64), warp_n = wid>>1 (x32); 4x4 m16n8k8 per warp.
// As[stage][128][ASTR]: frag banks 4*quad+t4+const -> conflict-free (ASTR%32==4)
// Bs[stage][32][BSTR]:  frag banks 8*t4+quad+const -> conflict-free (BSTR%32==8)
#define STAGES 3
#define BK 32
#define ASTR 36
#define BSTR 136
#define A_ST_FLOATS (128 * ASTR)                 // 4608
#define B_ST_FLOATS (BK * BSTR)                  // 4352
#define STAGE_FLOATS (A_ST_FLOATS + B_ST_FLOATS) // 8960
#define GEMM_SMEM_BYTES (STAGES * STAGE_FLOATS * 4)  // 107520

struct Frag { float c[4][4][4]; };

template <int KDIM, bool FC1>
__device__ __forceinline__ void gemm_core(
    const float* __restrict__ aBase,
    const float* __restrict__ bBase,
    int nTotal, int n0, int rs, int nr, Frag& F)
{
    extern __shared__ float dsm[];
    int tid = threadIdx.x;
    int lane = tid & 31, wid = tid >> 5;
    int quad = lane >> 2, t4 = lane & 3;
    int wm = (wid & 1) * 64, wn = (wid >> 1) * 32;

    // A: 2 threads/row, 16 floats (4 x 16B) each. acol0 is folded into aptr so the
    // global source and SMEM destination always agree (the R5/R8/R12 bug).
    int arow = tid >> 1;
    int acol0 = (tid & 1) * 16;
    const float* aptr;
    int aSz;                     // 16 = full copy, 0 = zero-fill
    if (FC1) {
        bool v = (arow < nr);
        aptr = (v ? (aBase + (size_t)g_rowToken[rs + arow] * KDIM) : aBase) + acol0;
        aSz = v ? 16 : 0;
    } else {
        int ar = rs + arow; if (ar >= N_ASSIGN) ar = N_ASSIGN - 1;
        aptr = aBase + (size_t)ar * KDIM + acol0;
        aSz = 16;
    }
    // B: 8 threads/row, 16 floats each; bcol0 folded into bptr (as always)
    int brow = tid >> 3;
    int bcol0 = (tid & 7) * 16;
    const float* bptr = bBase + (size_t)brow * nTotal + n0 + bcol0;

    uint32_t smem_base = (uint32_t)__cvta_generic_to_shared(dsm);
    uint32_t aDst0 = smem_base + (uint32_t)(arow * ASTR + acol0) * 4u;
    uint32_t bDst0 = smem_base + (uint32_t)(A_ST_FLOATS + brow * BSTR + bcol0) * 4u;

#pragma unroll
    for (int mi = 0; mi < 4; mi++)
#pragma unroll
        for (int ni = 0; ni < 4; ni++)
#pragma unroll
            for (int rr = 0; rr < 4; rr++) F.c[mi][ni][rr] = 0.f;

    const int NT = KDIM / BK;   // 32 (fc1) or 16 (fc2); both >= STAGES

    // ---- prologue: fill all STAGES stages with tiles 0..STAGES-1, one group each ----
#pragma unroll
    for (int p = 0; p < STAGES; p++) {
        uint32_t aD = aDst0 + (uint32_t)(p * STAGE_FLOATS) * 4u;
        uint32_t bD = bDst0 + (uint32_t)(p * STAGE_FLOATS) * 4u;
        const float* aS = aptr + p * BK;
        const float* bS = bptr + (size_t)(p * BK) * nTotal;
#pragma unroll
        for (int j = 0; j < 4; j++) cp16z(aD + j * 16u, aS + j * 4, aSz);
#pragma unroll
        for (int j = 0; j < 4; j++) cp16(bD + j * 16u, bS + j * 4);
        cp_commit();
    }

    int sc = 0;   // stage holding tile t
    for (int t = 0; t < NT; t++) {
        // pending groups: tiles t, t+1, t+2 (later ones possibly empty);
        // wait<2> completes tile t for this thread; barrier makes it CTA-visible.
        cp_wait<STAGES - 1>();
        __syncthreads();

        const float* As = dsm + sc * STAGE_FLOATS;
        const float* Bs = As + A_ST_FLOATS;
#pragma unroll
        for (int kk = 0; kk < BK / 8; kk++) {
            int k8 = kk * 8;
            uint32_t a[4][4], b[4][2];
#pragma unroll
            for (int mi = 0; mi < 4; mi++) {
                int r0 = wm + mi * 16 + quad;
                a[mi][0] = f2tf(As[r0 * ASTR + k8 + t4]);
                a[mi][1] = f2tf(As[(r0 + 8) * ASTR + k8 + t4]);
                a[mi][2] = f2tf(As[r0 * ASTR + k8 + t4 + 4]);
                a[mi][3] = f2tf(As[(r0 + 8) * ASTR + k8 + t4 + 4]);
            }
#pragma unroll
            for (int ni = 0; ni < 4; ni++) {
                int cc = wn + ni * 8 + quad;
                b[ni][0] = f2tf(Bs[(k8 + t4) * BSTR + cc]);
                b[ni][1] = f2tf(Bs[(k8 + t4 + 4) * BSTR + cc]);
            }
#pragma unroll
            for (int mi = 0; mi < 4; mi++)
#pragma unroll
                for (int ni = 0; ni < 4; ni++)
                    mma_tf32(F.c[mi][ni][0], F.c[mi][ni][1], F.c[mi][ni][2], F.c[mi][ni][3],
                             a[mi][0], a[mi][1], a[mi][2], a[mi][3],
                             b[ni][0], b[ni][1]);
        }

        // all threads done reading stage sc before anyone overwrites it
        __syncthreads();
        if (t + STAGES < NT) {
            uint32_t aD = aDst0 + (uint32_t)(sc * STAGE_FLOATS) * 4u;
            uint32_t bD = bDst0 + (uint32_t)(sc * STAGE_FLOATS) * 4u;
            const float* aS = aptr + (t + STAGES) * BK;
            const float* bS = bptr + (size_t)((t + STAGES) * BK) * nTotal;
#pragma unroll
            for (int j = 0; j < 4; j++) cp16z(aD + j * 16u, aS + j * 4, aSz);
#pragma unroll
            for (int j = 0; j < 4; j++) cp16(bD + j * 16u, bS + j * 4);
        }
        cp_commit();          // exactly one group per iteration (may be empty)

        sc = (sc + 1 == STAGES) ? 0 : sc + 1;
    }
}

// fc1: h = gelu(x_gathered @ w1[e] + b1[e]); grid (MAX_TILES, H_DIM/128)
__global__ void __launch_bounds__(256, 2)
fc1_mma(const float* __restrict__ x, const float* __restrict__ w1,
        const float* __restrict__ b1) {
    int tile = blockIdx.x;
    if (tile >= g_numTiles) return;
    int e = g_tileExpert[tile], rs = g_tileRowStart[tile], nr = g_tileRows[tile];
    int n0 = blockIdx.y * 128;

    Frag F;
    gemm_core<D_MODEL, true>(x, w1 + (size_t)e * D_MODEL * H_DIM, H_DIM, n0, rs, nr, F);

    int tid = threadIdx.x, lane = tid & 31, wid = tid >> 5;
    int quad = lane >> 2, t4 = lane & 3;
    int wm = (wid & 1) * 64, wn = (wid >> 1) * 32;
    const float* b1e = b1 + e * H_DIM + n0;
#pragma unroll
    for (int mi = 0; mi < 4; mi++) {
#pragma unroll
        for (int half = 0; half < 2; half++) {
            int m = wm + mi * 16 + quad + half * 8;
            if (m < nr) {
                float* hrow = g_h + (size_t)(rs + m) * H_DIM + n0;
#pragma unroll
                for (int ni = 0; ni < 4; ni++) {
                    int cc = wn + ni * 8 + 2 * t4;
                    float v0 = F.c[mi][ni][half * 2 + 0] + b1e[cc];
                    float v1 = F.c[mi][ni][half * 2 + 1] + b1e[cc + 1];
                    *(float2*)(hrow + cc) = make_float2(gelu_exact(v0), gelu_exact(v1));
                }
            }
        }
    }
}

// fc2: out[token] += tokw * (h @ w2[e] + b2[e]); grid (MAX_TILES, D_MODEL/128)
__global__ void __launch_bounds__(256, 2)
fc2_mma(const float* __restrict__ w2, const float* __restrict__ b2,
        float* __restrict__ out) {
    int tile = blockIdx.x;
    if (tile >= g_numTiles) return;
    int e = g_tileExpert[tile], rs = g_tileRowStart[tile], nr = g_tileRows[tile];
    int n0 = blockIdx.y * 128;

    Frag F;
    gemm_core<H_DIM, false>(g_h, w2 + (size_t)e * H_DIM * D_MODEL, D_MODEL, n0, rs, nr, F);

    int tid = threadIdx.x, lane = tid & 31, wid = tid >> 5;
    int quad = lane >> 2, t4 = lane & 3;
    int wm = (wid & 1) * 64, wn = (wid >> 1) * 32;
    const float* b2e = b2 + e * D_MODEL + n0;
#pragma unroll
    for (int mi = 0; mi < 4; mi++) {
#pragma unroll
        for (int half = 0; half < 2; half++) {
            int m = wm + mi * 16 + quad + half * 8;
            if (m < nr) {
                int token = g_rowToken[rs + m];
                float wgt = g_tokw[token];
                float* orow = out + (size_t)token * D_MODEL + n0;
#pragma unroll
                for (int ni = 0; ni < 4; ni++) {
                    int cc = wn + ni * 8 + 2 * t4;
                    float v0 = F.c[mi][ni][half * 2 + 0] + b2e[cc];
                    float v1 = F.c[mi][ni][half * 2 + 1] + b2e[cc + 1];
                    atomicAdd(&orow[cc], wgt * v0);
                    atomicAdd(&orow[cc + 1], wgt * v1);
                }
            }
        }
    }
}

// ------------------- launch -------------------
extern "C" void kernel_launch(void* const* d_in, const int* in_sizes, int n_in,
                              void* d_out, int out_size) {
    const float* x      = (const float*)d_in[0];
    const float* gate_w = (const float*)d_in[1];
    const float* w1     = (const float*)d_in[2];
    const float* b1     = (const float*)d_in[3];
    const float* w2     = (const float*)d_in[4];
    const float* b2     = (const float*)d_in[5];
    float* out = (float*)d_out;

    static bool attr_done = false;
    if (!attr_done) {
        cudaFuncSetAttribute(fc1_mma, cudaFuncAttributeMaxDynamicSharedMemorySize, GEMM_SMEM_BYTES);
        cudaFuncSetAttribute(fc2_mma, cudaFuncAttributeMaxDynamicSharedMemorySize, GEMM_SMEM_BYTES);
        attr_done = true;
    }

    init_kernel<<<(N_TOK * D_MODEL / 4 + 255) / 256, 256>>>(out);
    gate_kernel<<<N_TOK, 256>>>(x, gate_w);
    setup_kernel<<<1, 1>>>();
    scatter_kernel<<<(N_TOK + 255) / 256, 256>>>();
    {
        dim3 g(MAX_TILES, H_DIM / 128);
        fc1_mma<<<g, 256, GEMM_SMEM_BYTES>>>(x, w1, b1);
    }
    {
        dim3 g(MAX_TILES, D_MODEL / 128);
        fc2_mma<<<g, 256, GEMM_SMEM_BYTES>>>(w2, b2, out);
    }
}